// round 5
// baseline (speedup 1.0000x reference)
#include <cuda_runtime.h>
#include <cuda_fp16.h>

typedef unsigned long long ull;

#define DQ    512
#define H1Q   16
#define CQ    40
#define N_MAX 100000
#define NNZ_MAX 3200000
#define SCAN_B 1024
#define NBLK_SCAN ((N_MAX + SCAN_B - 1) / SCAN_B)   // 98

// ------------------------------ scratch -------------------------------------
__device__ uint2 g_X1h[N_MAX * 4];           // H @ W1, fp16
__device__ uint2 g_Zh [N_MAX * 4];           // relu(A @ X1 + b1), fp16
__device__ int   g_cnt[N_MAX];
__device__ int   g_ptr[N_MAX];
__device__ int   g_cur[N_MAX];
__device__ int   g_part[NBLK_SCAN];
__device__ int2  g_edges[NNZ_MAX];           // {col, val_bits} CSR-ordered

// ------------------------------ f32x2 helpers --------------------------------
__device__ __forceinline__ ull fma2(ull a, ull b, ull c) {
    ull d;
    asm("fma.rn.f32x2 %0, %1, %2, %3;" : "=l"(d) : "l"(a), "l"(b), "l"(c));
    return d;
}
__device__ __forceinline__ ull pack2(float x) {
    ull d;
    asm("mov.b64 %0, {%1, %1};" : "=l"(d) : "f"(x));
    return d;
}
__device__ __forceinline__ float2 unpack2(ull v) {
    float a, b;
    asm("mov.b64 {%0, %1}, %2;" : "=f"(a), "=f"(b) : "l"(v));
    return make_float2(a, b);
}
__device__ __forceinline__ unsigned h2pack(ull v) {
    float2 f = unpack2(v);
    __half2 h = __float22half2_rn(f);
    return *reinterpret_cast<unsigned*>(&h);
}
__device__ __forceinline__ float2 h2unpack(unsigned u) {
    __half2 h = *reinterpret_cast<__half2*>(&u);
    return __half22float2(h);
}

// ------------------------------ CSR build -----------------------------------
__global__ void hist_kernel(const int* __restrict__ rows, int nnz) {
    int e = blockIdx.x * blockDim.x + threadIdx.x;
    if (e < nnz) atomicAdd(&g_cnt[rows[e]], 1);
}

__global__ void scan1_kernel(int n) {
    __shared__ int s[SCAN_B];
    int tid = threadIdx.x;
    int i = blockIdx.x * SCAN_B + tid;
    int v = (i < n) ? g_cnt[i] : 0;
    s[tid] = v;
    __syncthreads();
#pragma unroll
    for (int off = 1; off < SCAN_B; off <<= 1) {
        int t = 0;
        if (tid >= off) t = s[tid - off];
        __syncthreads();
        if (tid >= off) s[tid] += t;
        __syncthreads();
    }
    if (i < n) g_ptr[i] = s[tid] - v;
    if (tid == SCAN_B - 1) g_part[blockIdx.x] = s[SCAN_B - 1];
}

__global__ void scan23_kernel(int n, int nb) {
    __shared__ int s[128];
    int tid = threadIdx.x;
    if (tid < 128) s[tid] = (tid < nb) ? g_part[tid] : 0;
    __syncthreads();
#pragma unroll
    for (int off = 1; off < 128; off <<= 1) {
        int u = 0;
        if (tid < 128 && tid >= off) u = s[tid - off];
        __syncthreads();
        if (tid < 128 && tid >= off) s[tid] += u;
        __syncthreads();
    }
    int i = blockIdx.x * blockDim.x + tid;
    if (i < n) {
        int blk = i >> 10;
        int base = (blk == 0) ? 0 : s[blk - 1];
        int p = g_ptr[i] + base;
        g_ptr[i] = p;
        g_cur[i] = p;
    }
}

// ------------------------------ fused gemm1 + scatter ------------------------
// gemm blocks: thread-per-row, 256 rows/block, k tiled by 32 through smem.
//   Global H loads are fully coalesced; smem reads are conflict-free LDS.128
//   (row stride 36 words -> bank offset 4*lane mod 32, disjoint spans).
__global__ void __launch_bounds__(256) gemm_scatter_kernel(
        const float* __restrict__ Hm, const float* __restrict__ W1,
        const int* __restrict__ rows, const int* __restrict__ cols,
        const float* __restrict__ vals, int n, int nnz, int gemm_blocks) {
    __shared__ ull   sW2[DQ * 8];       // 32KB  [k][pair]
    __shared__ float sH[256 * 36];      // 36KB  [row][36] (32 used + pad)

    if ((int)blockIdx.x < gemm_blocks) {
        for (int i = threadIdx.x; i < DQ * 8; i += blockDim.x)
            sW2[i] = reinterpret_cast<const ull*>(W1)[i];

        int tid   = threadIdx.x;
        int row   = blockIdx.x * 256 + tid;
        int rbase = blockIdx.x * 256;
        bool valid = row < n;

        ull acc[8];
        ull z = pack2(0.f);
#pragma unroll
        for (int p = 0; p < 8; p++) acc[p] = z;

        const float4* hg = reinterpret_cast<const float4*>(Hm);
        const ulonglong2* wv = reinterpret_cast<const ulonglong2*>(sW2);

        for (int t = 0; t < DQ / 32; t++) {        // 16 k-tiles of 32
            __syncthreads();
            // stage H[rbase..rbase+255][t*32..t*32+31] coalesced
#pragma unroll
            for (int j = 0; j < 8; j++) {
                int i = tid + 256 * j;             // 0..2047 float4s
                int r = i >> 3;                    // 8 float4 per row
                int c = i & 7;
                int grow = rbase + r;
                float4 v = (grow < n) ? hg[(size_t)grow * 128 + t * 8 + c]
                                      : make_float4(0, 0, 0, 0);
                *reinterpret_cast<float4*>(&sH[r * 36 + c * 4]) = v;
            }
            __syncthreads();
#pragma unroll
            for (int q = 0; q < 8; q++) {
                float4 h4 = *reinterpret_cast<const float4*>(&sH[tid * 36 + q * 4]);
                float hh[4] = {h4.x, h4.y, h4.z, h4.w};
#pragma unroll
                for (int j = 0; j < 4; j++) {
                    int k = t * 32 + q * 4 + j;
                    ull hp = pack2(hh[j]);
#pragma unroll
                    for (int p = 0; p < 4; p++) {
                        ulonglong2 w = wv[k * 4 + p];
                        acc[2 * p + 0] = fma2(hp, w.x, acc[2 * p + 0]);
                        acc[2 * p + 1] = fma2(hp, w.y, acc[2 * p + 1]);
                    }
                }
            }
        }

        if (valid) {
            uint2* o = &g_X1h[(size_t)row * 4];
#pragma unroll
            for (int q = 0; q < 4; q++)
                o[q] = make_uint2(h2pack(acc[2 * q]), h2pack(acc[2 * q + 1]));
        }
    } else {
        int e = (blockIdx.x - gemm_blocks) * blockDim.x + threadIdx.x;
        if (e < nnz) {
            int r = rows[e];
            int pos = atomicAdd(&g_cur[r], 1);
            g_edges[pos] = make_int2(cols[e], __float_as_int(vals[e]));
        }
    }
}

// ------------------------------ SpMM 1 --------------------------------------
__global__ void spmm1_kernel(const float* __restrict__ b1, int n) {
    int wg   = (blockIdx.x * blockDim.x + threadIdx.x) >> 5;
    int lane = threadIdx.x & 31;
    int rloc = lane >> 2, sub = lane & 3;
    int row  = wg * 8 + rloc;
    if (row >= n) return;

    int start = g_ptr[row];
    int deg   = g_cnt[row];
    const int2* ed = g_edges + start;
    const float4 b = reinterpret_cast<const float4*>(b1)[sub];

    float4 acc = make_float4(0, 0, 0, 0);
#pragma unroll 2
    for (int i = 0; i < deg; i++) {
        int2 e = ed[i];
        float v = __int_as_float(e.y);
        uint2 xh = g_X1h[(size_t)e.x * 4 + sub];
        float2 x0 = h2unpack(xh.x);
        float2 x1 = h2unpack(xh.y);
        acc.x = fmaf(v, x0.x, acc.x);
        acc.y = fmaf(v, x0.y, acc.y);
        acc.z = fmaf(v, x1.x, acc.z);
        acc.w = fmaf(v, x1.y, acc.w);
    }
    float2 z0 = make_float2(fmaxf(acc.x + b.x, 0.f), fmaxf(acc.y + b.y, 0.f));
    float2 z1 = make_float2(fmaxf(acc.z + b.z, 0.f), fmaxf(acc.w + b.w, 0.f));
    __half2 h0 = __float22half2_rn(z0);
    __half2 h1 = __float22half2_rn(z1);
    g_Zh[(size_t)row * 4 + sub] =
        make_uint2(*reinterpret_cast<unsigned*>(&h0), *reinterpret_cast<unsigned*>(&h1));
}

// ------------------------------ SpMM 2 + epilogue ----------------------------
__global__ void __launch_bounds__(256) spmm2_epi_kernel(
        const float* __restrict__ W2, const float* __restrict__ b2,
        float* __restrict__ out, int n) {
    __shared__ float sY[64 * 17];
    __shared__ float sW[H1Q * CQ];
    __shared__ float sB[CQ];

    for (int i = threadIdx.x; i < H1Q * CQ; i += blockDim.x) sW[i] = W2[i];
    if (threadIdx.x < CQ) sB[threadIdx.x] = b2[threadIdx.x];

    int warp  = threadIdx.x >> 5;
    int lane  = threadIdx.x & 31;
    int rloc  = warp * 8 + (lane >> 2);
    int sub   = lane & 3;
    int rbase = blockIdx.x * 64;
    int row   = rbase + rloc;

    float4 acc = make_float4(0, 0, 0, 0);
    if (row < n) {
        int start = g_ptr[row];
        int deg   = g_cnt[row];
        const int2* ed = g_edges + start;
#pragma unroll 2
        for (int i = 0; i < deg; i++) {
            int2 e = ed[i];
            float v = __int_as_float(e.y);
            uint2 xh = g_Zh[(size_t)e.x * 4 + sub];
            float2 x0 = h2unpack(xh.x);
            float2 x1 = h2unpack(xh.y);
            acc.x = fmaf(v, x0.x, acc.x);
            acc.y = fmaf(v, x0.y, acc.y);
            acc.z = fmaf(v, x1.x, acc.z);
            acc.w = fmaf(v, x1.y, acc.w);
        }
    }
    float* sy = &sY[rloc * 17 + sub * 4];
    sy[0] = acc.x; sy[1] = acc.y; sy[2] = acc.z; sy[3] = acc.w;
    __syncthreads();

    int t = threadIdx.x;
    if (t < 64 && rbase + t < n) {
        float y[16];
#pragma unroll
        for (int k = 0; k < 16; k++) y[k] = sY[t * 17 + k];

        float o[CQ];
#pragma unroll
        for (int c = 0; c < CQ; c++) o[c] = sB[c];
#pragma unroll
        for (int k = 0; k < H1Q; k++) {
            float h = y[k];
#pragma unroll
            for (int c = 0; c < CQ; c++) o[c] = fmaf(h, sW[k * CQ + c], o[c]);
        }
        float m = 0.f;
#pragma unroll
        for (int c = 0; c < CQ; c++) {
            o[c] = fmaxf(o[c], 0.f);
            m = fmaxf(m, o[c]);
        }
        float s = 0.f;
#pragma unroll
        for (int c = 0; c < CQ; c++) s += __expf(o[c] - m);
        float l = __logf(s) + m;

        float4* op = reinterpret_cast<float4*>(out + (size_t)(rbase + t) * CQ);
#pragma unroll
        for (int q = 0; q < CQ / 4; q++)
            op[q] = make_float4(o[4 * q] - l, o[4 * q + 1] - l,
                                o[4 * q + 2] - l, o[4 * q + 3] - l);
    }
}

// ---------------------------------------------------------------------------
// Inputs (metadata order): H, A_vals, W1, b1, W2, b2, A_rows, A_cols
// ---------------------------------------------------------------------------
extern "C" void kernel_launch(void* const* d_in, const int* in_sizes, int n_in,
                              void* d_out, int out_size) {
    const float* Hm     = (const float*)d_in[0];
    const float* A_vals = (const float*)d_in[1];
    const float* W1     = (const float*)d_in[2];
    const float* b1     = (const float*)d_in[3];
    const float* W2     = (const float*)d_in[4];
    const float* b2     = (const float*)d_in[5];
    const int*   A_rows = (const int*)d_in[6];
    const int*   A_cols = (const int*)d_in[7];

    int n   = in_sizes[0] / DQ;
    int nnz = in_sizes[1];
    float* out = (float*)d_out;

    int nb_scan = (n + SCAN_B - 1) / SCAN_B;

    void* cnt_ptr = nullptr;
    cudaGetSymbolAddress(&cnt_ptr, g_cnt);
    cudaMemsetAsync(cnt_ptr, 0, (size_t)n * sizeof(int), 0);

    hist_kernel<<<(nnz + 255) / 256, 256>>>(A_rows, nnz);
    scan1_kernel<<<nb_scan, SCAN_B>>>(n);
    scan23_kernel<<<(n + 255) / 256, 256>>>(n, nb_scan);

    int gemm_blocks    = (n + 255) / 256;
    int scatter_blocks = (nnz + 255) / 256;
    gemm_scatter_kernel<<<gemm_blocks + scatter_blocks, 256>>>(
        Hm, W1, A_rows, A_cols, A_vals, n, nnz, gemm_blocks);

    spmm1_kernel<<<(n + 63) / 64, 256>>>(b1, n);
    spmm2_epi_kernel<<<(n + 63) / 64, 256>>>(W2, b2, out, n);
}

// round 6
// speedup vs baseline: 1.0636x; 1.0636x over previous
#include <cuda_runtime.h>
#include <cuda_fp16.h>

typedef unsigned long long ull;

#define DQ    512
#define H1Q   16
#define CQ    40
#define N_MAX 100000
#define NNZ_MAX 3200000
#define SCAN_B 1024
#define NBLK_SCAN ((N_MAX + SCAN_B - 1) / SCAN_B)   // 98

#define TILE_K   16
#define NTILES   (DQ / TILE_K)   // 32
#define PADW     20              // floats per staged row (16 + 4 pad)

// ------------------------------ scratch -------------------------------------
__device__ uint2 g_X1h[N_MAX * 4];           // H @ W1, fp16
__device__ uint2 g_Zh [N_MAX * 4];           // relu(A @ X1 + b1), fp16
__device__ int   g_cnt[N_MAX];
__device__ int   g_ptr[N_MAX];
__device__ int   g_cur[N_MAX];
__device__ int   g_part[NBLK_SCAN];
__device__ int2  g_edges[NNZ_MAX];           // {col, val_bits} CSR-ordered

// ------------------------------ helpers -------------------------------------
__device__ __forceinline__ ull fma2(ull a, ull b, ull c) {
    ull d;
    asm("fma.rn.f32x2 %0, %1, %2, %3;" : "=l"(d) : "l"(a), "l"(b), "l"(c));
    return d;
}
__device__ __forceinline__ ull pack2(float x) {
    ull d;
    asm("mov.b64 %0, {%1, %1};" : "=l"(d) : "f"(x));
    return d;
}
__device__ __forceinline__ float2 unpack2(ull v) {
    float a, b;
    asm("mov.b64 {%0, %1}, %2;" : "=f"(a), "=f"(b) : "l"(v));
    return make_float2(a, b);
}
__device__ __forceinline__ unsigned h2pack(ull v) {
    float2 f = unpack2(v);
    __half2 h = __float22half2_rn(f);
    return *reinterpret_cast<unsigned*>(&h);
}
__device__ __forceinline__ float2 h2unpack(unsigned u) {
    __half2 h = *reinterpret_cast<__half2*>(&u);
    return __half22float2(h);
}
__device__ __forceinline__ unsigned smem_u32(const void* p) {
    return (unsigned)__cvta_generic_to_shared(p);
}
__device__ __forceinline__ void cp_async16(unsigned s, const void* g) {
    asm volatile("cp.async.cg.shared.global [%0], [%1], 16;" :: "r"(s), "l"(g));
}
__device__ __forceinline__ void cp_commit() {
    asm volatile("cp.async.commit_group;");
}
template <int N>
__device__ __forceinline__ void cp_wait() {
    asm volatile("cp.async.wait_group %0;" :: "n"(N));
}

// ------------------------------ fused GEMM + hist ----------------------------
// gemm blocks: thread-per-row, 256 rows/block, k tiled by 16 cols, cp.async
// double-buffered staging. hist blocks: degree histogram (atomics).
__global__ void __launch_bounds__(256) gemm_hist_kernel(
        const float* __restrict__ Hm, const float* __restrict__ W1,
        const int* __restrict__ rows, int n, int nnz, int gemm_blocks) {
    __shared__ ull   sW2[DQ * 8];            // 32KB  [k][pair0..7]
    __shared__ float sH[2][256 * PADW];      // 2 x 20KB

    if ((int)blockIdx.x < gemm_blocks) {
        int tid   = threadIdx.x;
        int rbase = blockIdx.x * 256;
        int row   = rbase + tid;

        // stage W (once)
        for (int i = tid; i < DQ * 8; i += 256)
            sW2[i] = reinterpret_cast<const ull*>(W1)[i];

        // issue tile 0
        {
#pragma unroll
            for (int j = 0; j < 4; j++) {
                int c = tid + 256 * j;           // 1024 chunks of 16B
                int r = c >> 2, q = c & 3;
                int grow = rbase + r;
                if (grow < n)
                    cp_async16(smem_u32(&sH[0][r * PADW + q * 4]),
                               Hm + (size_t)grow * DQ + q * 4);
            }
            cp_commit();
        }

        ull acc[8];
        ull z = pack2(0.f);
#pragma unroll
        for (int p = 0; p < 8; p++) acc[p] = z;

        const ulonglong2* wv = reinterpret_cast<const ulonglong2*>(sW2);

        for (int t = 0; t < NTILES; t++) {
            int buf = t & 1;
            if (t + 1 < NTILES) {
                int nb = buf ^ 1;
#pragma unroll
                for (int j = 0; j < 4; j++) {
                    int c = tid + 256 * j;
                    int r = c >> 2, q = c & 3;
                    int grow = rbase + r;
                    if (grow < n)
                        cp_async16(smem_u32(&sH[nb][r * PADW + q * 4]),
                                   Hm + (size_t)grow * DQ + (t + 1) * TILE_K + q * 4);
                }
                cp_commit();
                cp_wait<1>();
            } else {
                cp_wait<0>();
            }
            __syncthreads();   // tile t visible to all (also covers sW2 on t=0)

            const float* hrow = &sH[buf][tid * PADW];
#pragma unroll
            for (int q = 0; q < 4; q++) {
                float4 h4 = *reinterpret_cast<const float4*>(hrow + q * 4);
                float hh[4] = {h4.x, h4.y, h4.z, h4.w};
#pragma unroll
                for (int j = 0; j < 4; j++) {
                    int k = t * TILE_K + q * 4 + j;
                    ull hp = pack2(hh[j]);
#pragma unroll
                    for (int p = 0; p < 4; p++) {
                        ulonglong2 w = wv[k * 4 + p];
                        acc[2 * p + 0] = fma2(hp, w.x, acc[2 * p + 0]);
                        acc[2 * p + 1] = fma2(hp, w.y, acc[2 * p + 1]);
                    }
                }
            }
            __syncthreads();   // done reading buf before it is overwritten
        }

        if (row < n) {
            uint2* o = &g_X1h[(size_t)row * 4];
#pragma unroll
            for (int q = 0; q < 4; q++)
                o[q] = make_uint2(h2pack(acc[2 * q]), h2pack(acc[2 * q + 1]));
        }
    } else {
        int e = (blockIdx.x - gemm_blocks) * 256 + threadIdx.x;
        if (e < nnz) atomicAdd(&g_cnt[rows[e]], 1);
    }
}

// ------------------------------ CSR build -----------------------------------
__global__ void scan1_kernel(int n) {
    __shared__ int s[SCAN_B];
    int tid = threadIdx.x;
    int i = blockIdx.x * SCAN_B + tid;
    int v = (i < n) ? g_cnt[i] : 0;
    s[tid] = v;
    __syncthreads();
#pragma unroll
    for (int off = 1; off < SCAN_B; off <<= 1) {
        int t = 0;
        if (tid >= off) t = s[tid - off];
        __syncthreads();
        if (tid >= off) s[tid] += t;
        __syncthreads();
    }
    if (i < n) g_ptr[i] = s[tid] - v;
    if (tid == SCAN_B - 1) g_part[blockIdx.x] = s[SCAN_B - 1];
}

__global__ void scan23_kernel(int n, int nb) {
    __shared__ int s[128];
    int tid = threadIdx.x;
    if (tid < 128) s[tid] = (tid < nb) ? g_part[tid] : 0;
    __syncthreads();
#pragma unroll
    for (int off = 1; off < 128; off <<= 1) {
        int u = 0;
        if (tid < 128 && tid >= off) u = s[tid - off];
        __syncthreads();
        if (tid < 128 && tid >= off) s[tid] += u;
        __syncthreads();
    }
    int i = blockIdx.x * blockDim.x + tid;
    if (i < n) {
        int blk = i >> 10;
        int base = (blk == 0) ? 0 : s[blk - 1];
        int p = g_ptr[i] + base;
        g_ptr[i] = p;
        g_cur[i] = p;
    }
}

__global__ void scatter_kernel(const int* __restrict__ rows,
                               const int* __restrict__ cols,
                               const float* __restrict__ vals, int nnz) {
    int e = blockIdx.x * blockDim.x + threadIdx.x;
    if (e >= nnz) return;
    int r = rows[e];
    int pos = atomicAdd(&g_cur[r], 1);
    g_edges[pos] = make_int2(cols[e], __float_as_int(vals[e]));
}

// ------------------------------ SpMM 1 --------------------------------------
__global__ void spmm1_kernel(const float* __restrict__ b1, int n) {
    int wg   = (blockIdx.x * blockDim.x + threadIdx.x) >> 5;
    int lane = threadIdx.x & 31;
    int rloc = lane >> 2, sub = lane & 3;
    int row  = wg * 8 + rloc;
    if (row >= n) return;

    int start = g_ptr[row];
    int deg   = g_cnt[row];
    const int2* ed = g_edges + start;
    const float4 b = reinterpret_cast<const float4*>(b1)[sub];

    float4 acc = make_float4(0, 0, 0, 0);
#pragma unroll 2
    for (int i = 0; i < deg; i++) {
        int2 e = ed[i];
        float v = __int_as_float(e.y);
        uint2 xh = g_X1h[(size_t)e.x * 4 + sub];
        float2 x0 = h2unpack(xh.x);
        float2 x1 = h2unpack(xh.y);
        acc.x = fmaf(v, x0.x, acc.x);
        acc.y = fmaf(v, x0.y, acc.y);
        acc.z = fmaf(v, x1.x, acc.z);
        acc.w = fmaf(v, x1.y, acc.w);
    }
    float2 z0 = make_float2(fmaxf(acc.x + b.x, 0.f), fmaxf(acc.y + b.y, 0.f));
    float2 z1 = make_float2(fmaxf(acc.z + b.z, 0.f), fmaxf(acc.w + b.w, 0.f));
    __half2 h0 = __float22half2_rn(z0);
    __half2 h1 = __float22half2_rn(z1);
    g_Zh[(size_t)row * 4 + sub] =
        make_uint2(*reinterpret_cast<unsigned*>(&h0), *reinterpret_cast<unsigned*>(&h1));
}

// ------------------------------ SpMM 2 + epilogue ----------------------------
__global__ void __launch_bounds__(256) spmm2_epi_kernel(
        const float* __restrict__ W2, const float* __restrict__ b2,
        float* __restrict__ out, int n) {
    __shared__ float sY[64 * 17];
    __shared__ float sW[H1Q * CQ];
    __shared__ float sB[CQ];

    for (int i = threadIdx.x; i < H1Q * CQ; i += blockDim.x) sW[i] = W2[i];
    if (threadIdx.x < CQ) sB[threadIdx.x] = b2[threadIdx.x];

    int warp  = threadIdx.x >> 5;
    int lane  = threadIdx.x & 31;
    int rloc  = warp * 8 + (lane >> 2);
    int sub   = lane & 3;
    int rbase = blockIdx.x * 64;
    int row   = rbase + rloc;

    float4 acc = make_float4(0, 0, 0, 0);
    if (row < n) {
        int start = g_ptr[row];
        int deg   = g_cnt[row];
        const int2* ed = g_edges + start;
#pragma unroll 2
        for (int i = 0; i < deg; i++) {
            int2 e = ed[i];
            float v = __int_as_float(e.y);
            uint2 xh = g_Zh[(size_t)e.x * 4 + sub];
            float2 x0 = h2unpack(xh.x);
            float2 x1 = h2unpack(xh.y);
            acc.x = fmaf(v, x0.x, acc.x);
            acc.y = fmaf(v, x0.y, acc.y);
            acc.z = fmaf(v, x1.x, acc.z);
            acc.w = fmaf(v, x1.y, acc.w);
        }
    }
    float* sy = &sY[rloc * 17 + sub * 4];
    sy[0] = acc.x; sy[1] = acc.y; sy[2] = acc.z; sy[3] = acc.w;
    __syncthreads();

    int t = threadIdx.x;
    if (t < 64 && rbase + t < n) {
        float y[16];
#pragma unroll
        for (int k = 0; k < 16; k++) y[k] = sY[t * 17 + k];

        float o[CQ];
#pragma unroll
        for (int c = 0; c < CQ; c++) o[c] = sB[c];
#pragma unroll
        for (int k = 0; k < H1Q; k++) {
            float h = y[k];
#pragma unroll
            for (int c = 0; c < CQ; c++) o[c] = fmaf(h, sW[k * CQ + c], o[c]);
        }
        float m = 0.f;
#pragma unroll
        for (int c = 0; c < CQ; c++) {
            o[c] = fmaxf(o[c], 0.f);
            m = fmaxf(m, o[c]);
        }
        float s = 0.f;
#pragma unroll
        for (int c = 0; c < CQ; c++) s += __expf(o[c] - m);
        float l = __logf(s) + m;

        float4* op = reinterpret_cast<float4*>(out + (size_t)(rbase + t) * CQ);
#pragma unroll
        for (int q = 0; q < CQ / 4; q++)
            op[q] = make_float4(o[4 * q] - l, o[4 * q + 1] - l,
                                o[4 * q + 2] - l, o[4 * q + 3] - l);
    }
}

// ---------------------------------------------------------------------------
// Inputs (metadata order): H, A_vals, W1, b1, W2, b2, A_rows, A_cols
// ---------------------------------------------------------------------------
extern "C" void kernel_launch(void* const* d_in, const int* in_sizes, int n_in,
                              void* d_out, int out_size) {
    const float* Hm     = (const float*)d_in[0];
    const float* A_vals = (const float*)d_in[1];
    const float* W1     = (const float*)d_in[2];
    const float* b1     = (const float*)d_in[3];
    const float* W2     = (const float*)d_in[4];
    const float* b2     = (const float*)d_in[5];
    const int*   A_rows = (const int*)d_in[6];
    const int*   A_cols = (const int*)d_in[7];

    int n   = in_sizes[0] / DQ;
    int nnz = in_sizes[1];
    float* out = (float*)d_out;

    int nb_scan = (n + SCAN_B - 1) / SCAN_B;

    void* cnt_ptr = nullptr;
    cudaGetSymbolAddress(&cnt_ptr, g_cnt);
    cudaMemsetAsync(cnt_ptr, 0, (size_t)n * sizeof(int), 0);

    int gemm_blocks = (n + 255) / 256;
    int hist_blocks = (nnz + 255) / 256;
    gemm_hist_kernel<<<gemm_blocks + hist_blocks, 256>>>(
        Hm, W1, A_rows, n, nnz, gemm_blocks);

    scan1_kernel<<<nb_scan, SCAN_B>>>(n);
    scan23_kernel<<<(n + 255) / 256, 256>>>(n, nb_scan);
    scatter_kernel<<<(nnz + 255) / 256, 256>>>(A_rows, A_cols, A_vals, nnz);

    spmm1_kernel<<<(n + 63) / 64, 256>>>(b1, n);
    spmm2_epi_kernel<<<(n + 63) / 64, 256>>>(W2, b2, out, n);
}

// round 7
// speedup vs baseline: 1.0774x; 1.0130x over previous
#include <cuda_runtime.h>
#include <cuda_fp16.h>

typedef unsigned long long ull;

#define DQ    512
#define H1Q   16
#define CQ    40
#define N_MAX 100000
#define NNZ_MAX 3200000
#define SCAN_B 1024
#define NBLK_SCAN ((N_MAX + SCAN_B - 1) / SCAN_B)   // 98

#define TILE_K   8
#define NTILES   (DQ / TILE_K)   // 64
#define PADW     12              // floats per staged row (8 + 4 pad)

// ------------------------------ scratch -------------------------------------
__device__ uint2 g_X1h[N_MAX * 4];           // H @ W1, fp16
__device__ uint2 g_Zh [N_MAX * 4];           // relu(A @ X1 + b1), fp16
__device__ int   g_cnt[N_MAX];
__device__ int   g_ptr[N_MAX];
__device__ int   g_cur[N_MAX];
__device__ int   g_part[NBLK_SCAN];
__device__ int2  g_edges[NNZ_MAX];           // {col, val_bits} CSR-ordered

// ------------------------------ helpers -------------------------------------
__device__ __forceinline__ ull fma2(ull a, ull b, ull c) {
    ull d;
    asm("fma.rn.f32x2 %0, %1, %2, %3;" : "=l"(d) : "l"(a), "l"(b), "l"(c));
    return d;
}
__device__ __forceinline__ ull pack2(float x) {
    ull d;
    asm("mov.b64 %0, {%1, %1};" : "=l"(d) : "f"(x));
    return d;
}
__device__ __forceinline__ float2 unpack2(ull v) {
    float a, b;
    asm("mov.b64 {%0, %1}, %2;" : "=f"(a), "=f"(b) : "l"(v));
    return make_float2(a, b);
}
__device__ __forceinline__ unsigned h2pack(ull v) {
    float2 f = unpack2(v);
    __half2 h = __float22half2_rn(f);
    return *reinterpret_cast<unsigned*>(&h);
}
__device__ __forceinline__ float2 h2unpack(unsigned u) {
    __half2 h = *reinterpret_cast<__half2*>(&u);
    return __half22float2(h);
}
__device__ __forceinline__ unsigned smem_u32(const void* p) {
    return (unsigned)__cvta_generic_to_shared(p);
}
__device__ __forceinline__ void cp_async16(unsigned s, const void* g) {
    asm volatile("cp.async.cg.shared.global [%0], [%1], 16;" :: "r"(s), "l"(g));
}
__device__ __forceinline__ void cp_commit() {
    asm volatile("cp.async.commit_group;");
}
template <int N>
__device__ __forceinline__ void cp_wait() {
    asm volatile("cp.async.wait_group %0;" :: "n"(N));
}

// ------------------------------ hist (4 edges/thread) ------------------------
__global__ void hist_kernel(const int* __restrict__ rows, int nnz) {
    int idx = blockIdx.x * blockDim.x + threadIdx.x;
    int nv = nnz >> 2;
    if (idx < nv) {
        int4 r4 = reinterpret_cast<const int4*>(rows)[idx];
        atomicAdd(&g_cnt[r4.x], 1);
        atomicAdd(&g_cnt[r4.y], 1);
        atomicAdd(&g_cnt[r4.z], 1);
        atomicAdd(&g_cnt[r4.w], 1);
    } else if (idx == nv) {
        for (int e = nv * 4; e < nnz; e++) atomicAdd(&g_cnt[rows[e]], 1);
    }
}

// ------------------------------ scans ---------------------------------------
__global__ void scan1_kernel(int n) {
    __shared__ int s[SCAN_B];
    int tid = threadIdx.x;
    int i = blockIdx.x * SCAN_B + tid;
    int v = (i < n) ? g_cnt[i] : 0;
    s[tid] = v;
    __syncthreads();
#pragma unroll
    for (int off = 1; off < SCAN_B; off <<= 1) {
        int t = 0;
        if (tid >= off) t = s[tid - off];
        __syncthreads();
        if (tid >= off) s[tid] += t;
        __syncthreads();
    }
    if (i < n) g_ptr[i] = s[tid] - v;
    if (tid == SCAN_B - 1) g_part[blockIdx.x] = s[SCAN_B - 1];
}

__global__ void scan23_kernel(int n, int nb) {
    __shared__ int s[128];
    int tid = threadIdx.x;
    if (tid < 128) s[tid] = (tid < nb) ? g_part[tid] : 0;
    __syncthreads();
#pragma unroll
    for (int off = 1; off < 128; off <<= 1) {
        int u = 0;
        if (tid < 128 && tid >= off) u = s[tid - off];
        __syncthreads();
        if (tid < 128 && tid >= off) s[tid] += u;
        __syncthreads();
    }
    int i = blockIdx.x * blockDim.x + tid;
    if (i < n) {
        int blk = i >> 10;
        int base = (blk == 0) ? 0 : s[blk - 1];
        int p = g_ptr[i] + base;
        g_ptr[i] = p;
        g_cur[i] = p;
    }
}

// ------------------------------ fused GEMM + scatter -------------------------
// gemm blocks: thread-per-row, 256 rows/block, TILE_K=8 double-buffered
// cp.async (smem 56KB -> 4 CTA/SM). scatter blocks: 4 edges/thread (MLP=4).
__global__ void __launch_bounds__(256) gemm_scatter_kernel(
        const float* __restrict__ Hm, const float* __restrict__ W1,
        const int* __restrict__ rows, const int* __restrict__ cols,
        const float* __restrict__ vals, int n, int nnz, int gemm_blocks) {
    __shared__ ull   sW2[DQ * 8];           // 32KB
    __shared__ float sH[2][256 * PADW];     // 2 x 12KB

    if ((int)blockIdx.x < gemm_blocks) {
        int tid   = threadIdx.x;
        int rbase = blockIdx.x * 256;
        int row   = rbase + tid;

        for (int i = tid; i < DQ * 8; i += 256)
            sW2[i] = reinterpret_cast<const ull*>(W1)[i];

        // stage tile 0
#pragma unroll
        for (int j = 0; j < 2; j++) {
            int c = tid + 256 * j;
            int r = c >> 1, q = c & 1;
            int grow = rbase + r;
            if (grow < n)
                cp_async16(smem_u32(&sH[0][r * PADW + q * 4]),
                           Hm + (size_t)grow * DQ + q * 4);
        }
        cp_commit();

        ull acc[8];
        ull z = pack2(0.f);
#pragma unroll
        for (int p = 0; p < 8; p++) acc[p] = z;

        const ulonglong2* wv = reinterpret_cast<const ulonglong2*>(sW2);

        for (int t = 0; t < NTILES; t++) {
            int buf = t & 1;
            if (t + 1 < NTILES) {
                int nb = buf ^ 1;
#pragma unroll
                for (int j = 0; j < 2; j++) {
                    int c = tid + 256 * j;
                    int r = c >> 1, q = c & 1;
                    int grow = rbase + r;
                    if (grow < n)
                        cp_async16(smem_u32(&sH[nb][r * PADW + q * 4]),
                                   Hm + (size_t)grow * DQ + (t + 1) * TILE_K + q * 4);
                }
                cp_commit();
                cp_wait<1>();
            } else {
                cp_wait<0>();
            }
            __syncthreads();

            const float* hrow = &sH[buf][tid * PADW];
#pragma unroll
            for (int q = 0; q < 2; q++) {
                float4 h4 = *reinterpret_cast<const float4*>(hrow + q * 4);
                float hh[4] = {h4.x, h4.y, h4.z, h4.w};
#pragma unroll
                for (int j = 0; j < 4; j++) {
                    int k = t * TILE_K + q * 4 + j;
                    ull hp = pack2(hh[j]);
#pragma unroll
                    for (int p = 0; p < 4; p++) {
                        ulonglong2 w = wv[k * 4 + p];
                        acc[2 * p + 0] = fma2(hp, w.x, acc[2 * p + 0]);
                        acc[2 * p + 1] = fma2(hp, w.y, acc[2 * p + 1]);
                    }
                }
            }
            __syncthreads();
        }

        if (row < n) {
            uint2* o = &g_X1h[(size_t)row * 4];
#pragma unroll
            for (int q = 0; q < 4; q++)
                o[q] = make_uint2(h2pack(acc[2 * q]), h2pack(acc[2 * q + 1]));
        }
    } else {
        int idx = (blockIdx.x - gemm_blocks) * 256 + threadIdx.x;
        int nv = nnz >> 2;
        if (idx < nv) {
            int4   r4 = reinterpret_cast<const int4*>(rows)[idx];
            int4   c4 = reinterpret_cast<const int4*>(cols)[idx];
            float4 v4 = reinterpret_cast<const float4*>(vals)[idx];
            int p0 = atomicAdd(&g_cur[r4.x], 1);
            int p1 = atomicAdd(&g_cur[r4.y], 1);
            int p2 = atomicAdd(&g_cur[r4.z], 1);
            int p3 = atomicAdd(&g_cur[r4.w], 1);
            g_edges[p0] = make_int2(c4.x, __float_as_int(v4.x));
            g_edges[p1] = make_int2(c4.y, __float_as_int(v4.y));
            g_edges[p2] = make_int2(c4.z, __float_as_int(v4.z));
            g_edges[p3] = make_int2(c4.w, __float_as_int(v4.w));
        } else if (idx == nv) {
            for (int e = nv * 4; e < nnz; e++) {
                int p = atomicAdd(&g_cur[rows[e]], 1);
                g_edges[p] = make_int2(cols[e], __float_as_int(vals[e]));
            }
        }
    }
}

// ------------------------------ SpMM 1 (MLP=4) -------------------------------
__global__ void spmm1_kernel(const float* __restrict__ b1, int n) {
    int wg   = (blockIdx.x * blockDim.x + threadIdx.x) >> 5;
    int lane = threadIdx.x & 31;
    int rloc = lane >> 2, sub = lane & 3;
    int row  = wg * 8 + rloc;
    if (row >= n) return;

    int start = g_ptr[row];
    int deg   = g_cnt[row];
    const int2* ed = g_edges + start;
    const float4 b = reinterpret_cast<const float4*>(b1)[sub];

    float4 acc = make_float4(0, 0, 0, 0);
    int i = 0;
    for (; i + 4 <= deg; i += 4) {
        int2 e0 = ed[i + 0], e1 = ed[i + 1], e2 = ed[i + 2], e3 = ed[i + 3];
        uint2 x0 = g_X1h[(size_t)e0.x * 4 + sub];
        uint2 x1 = g_X1h[(size_t)e1.x * 4 + sub];
        uint2 x2 = g_X1h[(size_t)e2.x * 4 + sub];
        uint2 x3 = g_X1h[(size_t)e3.x * 4 + sub];
        float v0 = __int_as_float(e0.y), v1 = __int_as_float(e1.y);
        float v2 = __int_as_float(e2.y), v3 = __int_as_float(e3.y);
        float2 a0 = h2unpack(x0.x), b0 = h2unpack(x0.y);
        float2 a1 = h2unpack(x1.x), b1h = h2unpack(x1.y);
        float2 a2 = h2unpack(x2.x), b2h = h2unpack(x2.y);
        float2 a3 = h2unpack(x3.x), b3h = h2unpack(x3.y);
        acc.x = fmaf(v0, a0.x, acc.x); acc.y = fmaf(v0, a0.y, acc.y);
        acc.z = fmaf(v0, b0.x, acc.z); acc.w = fmaf(v0, b0.y, acc.w);
        acc.x = fmaf(v1, a1.x, acc.x); acc.y = fmaf(v1, a1.y, acc.y);
        acc.z = fmaf(v1, b1h.x, acc.z); acc.w = fmaf(v1, b1h.y, acc.w);
        acc.x = fmaf(v2, a2.x, acc.x); acc.y = fmaf(v2, a2.y, acc.y);
        acc.z = fmaf(v2, b2h.x, acc.z); acc.w = fmaf(v2, b2h.y, acc.w);
        acc.x = fmaf(v3, a3.x, acc.x); acc.y = fmaf(v3, a3.y, acc.y);
        acc.z = fmaf(v3, b3h.x, acc.z); acc.w = fmaf(v3, b3h.y, acc.w);
    }
    for (; i < deg; i++) {
        int2 e = ed[i];
        float v = __int_as_float(e.y);
        uint2 xh = g_X1h[(size_t)e.x * 4 + sub];
        float2 x0 = h2unpack(xh.x), x1 = h2unpack(xh.y);
        acc.x = fmaf(v, x0.x, acc.x); acc.y = fmaf(v, x0.y, acc.y);
        acc.z = fmaf(v, x1.x, acc.z); acc.w = fmaf(v, x1.y, acc.w);
    }
    float2 z0 = make_float2(fmaxf(acc.x + b.x, 0.f), fmaxf(acc.y + b.y, 0.f));
    float2 z1 = make_float2(fmaxf(acc.z + b.z, 0.f), fmaxf(acc.w + b.w, 0.f));
    __half2 h0 = __float22half2_rn(z0);
    __half2 h1 = __float22half2_rn(z1);
    g_Zh[(size_t)row * 4 + sub] =
        make_uint2(*reinterpret_cast<unsigned*>(&h0), *reinterpret_cast<unsigned*>(&h1));
}

// ------------------------------ SpMM 2 + epilogue (MLP=4) --------------------
__global__ void __launch_bounds__(256) spmm2_epi_kernel(
        const float* __restrict__ W2, const float* __restrict__ b2,
        float* __restrict__ out, int n) {
    __shared__ float sY[64 * 17];
    __shared__ float sW[H1Q * CQ];
    __shared__ float sB[CQ];

    for (int i = threadIdx.x; i < H1Q * CQ; i += blockDim.x) sW[i] = W2[i];
    if (threadIdx.x < CQ) sB[threadIdx.x] = b2[threadIdx.x];

    int warp  = threadIdx.x >> 5;
    int lane  = threadIdx.x & 31;
    int rloc  = warp * 8 + (lane >> 2);
    int sub   = lane & 3;
    int rbase = blockIdx.x * 64;
    int row   = rbase + rloc;

    float4 acc = make_float4(0, 0, 0, 0);
    if (row < n) {
        int start = g_ptr[row];
        int deg   = g_cnt[row];
        const int2* ed = g_edges + start;
        int i = 0;
        for (; i + 4 <= deg; i += 4) {
            int2 e0 = ed[i + 0], e1 = ed[i + 1], e2 = ed[i + 2], e3 = ed[i + 3];
            uint2 x0 = g_Zh[(size_t)e0.x * 4 + sub];
            uint2 x1 = g_Zh[(size_t)e1.x * 4 + sub];
            uint2 x2 = g_Zh[(size_t)e2.x * 4 + sub];
            uint2 x3 = g_Zh[(size_t)e3.x * 4 + sub];
            float v0 = __int_as_float(e0.y), v1 = __int_as_float(e1.y);
            float v2 = __int_as_float(e2.y), v3 = __int_as_float(e3.y);
            float2 a0 = h2unpack(x0.x), c0 = h2unpack(x0.y);
            float2 a1 = h2unpack(x1.x), c1 = h2unpack(x1.y);
            float2 a2 = h2unpack(x2.x), c2 = h2unpack(x2.y);
            float2 a3 = h2unpack(x3.x), c3 = h2unpack(x3.y);
            acc.x = fmaf(v0, a0.x, acc.x); acc.y = fmaf(v0, a0.y, acc.y);
            acc.z = fmaf(v0, c0.x, acc.z); acc.w = fmaf(v0, c0.y, acc.w);
            acc.x = fmaf(v1, a1.x, acc.x); acc.y = fmaf(v1, a1.y, acc.y);
            acc.z = fmaf(v1, c1.x, acc.z); acc.w = fmaf(v1, c1.y, acc.w);
            acc.x = fmaf(v2, a2.x, acc.x); acc.y = fmaf(v2, a2.y, acc.y);
            acc.z = fmaf(v2, c2.x, acc.z); acc.w = fmaf(v2, c2.y, acc.w);
            acc.x = fmaf(v3, a3.x, acc.x); acc.y = fmaf(v3, a3.y, acc.y);
            acc.z = fmaf(v3, c3.x, acc.z); acc.w = fmaf(v3, c3.y, acc.w);
        }
        for (; i < deg; i++) {
            int2 e = ed[i];
            float v = __int_as_float(e.y);
            uint2 xh = g_Zh[(size_t)e.x * 4 + sub];
            float2 x0 = h2unpack(xh.x), x1 = h2unpack(xh.y);
            acc.x = fmaf(v, x0.x, acc.x); acc.y = fmaf(v, x0.y, acc.y);
            acc.z = fmaf(v, x1.x, acc.z); acc.w = fmaf(v, x1.y, acc.w);
        }
    }
    float* sy = &sY[rloc * 17 + sub * 4];
    sy[0] = acc.x; sy[1] = acc.y; sy[2] = acc.z; sy[3] = acc.w;
    __syncthreads();

    int t = threadIdx.x;
    if (t < 64 && rbase + t < n) {
        float y[16];
#pragma unroll
        for (int k = 0; k < 16; k++) y[k] = sY[t * 17 + k];

        float o[CQ];
#pragma unroll
        for (int c = 0; c < CQ; c++) o[c] = sB[c];
#pragma unroll
        for (int k = 0; k < H1Q; k++) {
            float h = y[k];
#pragma unroll
            for (int c = 0; c < CQ; c++) o[c] = fmaf(h, sW[k * CQ + c], o[c]);
        }
        float m = 0.f;
#pragma unroll
        for (int c = 0; c < CQ; c++) {
            o[c] = fmaxf(o[c], 0.f);
            m = fmaxf(m, o[c]);
        }
        float s = 0.f;
#pragma unroll
        for (int c = 0; c < CQ; c++) s += __expf(o[c] - m);
        float l = __logf(s) + m;

        float4* op = reinterpret_cast<float4*>(out + (size_t)(rbase + t) * CQ);
#pragma unroll
        for (int q = 0; q < CQ / 4; q++)
            op[q] = make_float4(o[4 * q] - l, o[4 * q + 1] - l,
                                o[4 * q + 2] - l, o[4 * q + 3] - l);
    }
}

// ---------------------------------------------------------------------------
// Inputs (metadata order): H, A_vals, W1, b1, W2, b2, A_rows, A_cols
// ---------------------------------------------------------------------------
extern "C" void kernel_launch(void* const* d_in, const int* in_sizes, int n_in,
                              void* d_out, int out_size) {
    const float* Hm     = (const float*)d_in[0];
    const float* A_vals = (const float*)d_in[1];
    const float* W1     = (const float*)d_in[2];
    const float* b1     = (const float*)d_in[3];
    const float* W2     = (const float*)d_in[4];
    const float* b2     = (const float*)d_in[5];
    const int*   A_rows = (const int*)d_in[6];
    const int*   A_cols = (const int*)d_in[7];

    int n   = in_sizes[0] / DQ;
    int nnz = in_sizes[1];
    float* out = (float*)d_out;

    int nb_scan = (n + SCAN_B - 1) / SCAN_B;

    void* cnt_ptr = nullptr;
    cudaGetSymbolAddress(&cnt_ptr, g_cnt);
    cudaMemsetAsync(cnt_ptr, 0, (size_t)n * sizeof(int), 0);

    hist_kernel<<<(nnz / 4 + 256) / 256, 256>>>(A_rows, nnz);
    scan1_kernel<<<nb_scan, SCAN_B>>>(n);
    scan23_kernel<<<(n + 255) / 256, 256>>>(n, nb_scan);

    int gemm_blocks    = (n + 255) / 256;
    int scatter_blocks = (nnz / 4 + 256) / 256;
    gemm_scatter_kernel<<<gemm_blocks + scatter_blocks, 256>>>(
        Hm, W1, A_rows, A_cols, A_vals, n, nnz, gemm_blocks);

    spmm1_kernel<<<(n + 63) / 64, 256>>>(b1, n);
    spmm2_epi_kernel<<<(n + 63) / 64, 256>>>(W2, b2, out, n);
}

// round 8
// speedup vs baseline: 1.2232x; 1.1354x over previous
#include <cuda_runtime.h>
#include <cuda_fp16.h>

typedef unsigned long long ull;

#define DQ    512
#define H1Q   16
#define CQ    40
#define N_MAX 100000
#define NNZ_MAX 3200000
#define SCAN_B 1024
#define NBLK_SCAN ((N_MAX + SCAN_B - 1) / SCAN_B)   // 98

#define TK     16                 // k-cols per tile
#define NT     (DQ / TK)          // 32 tiles
#define PADW   20                 // floats per staged row

// ------------------------------ scratch -------------------------------------
__device__ uint2 g_X1h[N_MAX * 4];           // H @ W1, fp16
__device__ uint2 g_Zh [N_MAX * 4];           // relu(A @ X1 + b1), fp16
__device__ int   g_cnt[N_MAX];
__device__ int   g_ptr[N_MAX];
__device__ int   g_cur[N_MAX];
__device__ int   g_part[NBLK_SCAN];
__device__ int2  g_edges[NNZ_MAX];           // {col, val_bits} CSR-ordered

// ------------------------------ helpers -------------------------------------
__device__ __forceinline__ ull fma2(ull a, ull b, ull c) {
    ull d;
    asm("fma.rn.f32x2 %0, %1, %2, %3;" : "=l"(d) : "l"(a), "l"(b), "l"(c));
    return d;
}
__device__ __forceinline__ ull pack2(float x) {
    ull d;
    asm("mov.b64 %0, {%1, %1};" : "=l"(d) : "f"(x));
    return d;
}
__device__ __forceinline__ float2 unpack2(ull v) {
    float a, b;
    asm("mov.b64 {%0, %1}, %2;" : "=f"(a), "=f"(b) : "l"(v));
    return make_float2(a, b);
}
__device__ __forceinline__ unsigned h2pack(ull v) {
    float2 f = unpack2(v);
    __half2 h = __float22half2_rn(f);
    return *reinterpret_cast<unsigned*>(&h);
}
__device__ __forceinline__ float2 h2unpack(unsigned u) {
    __half2 h = *reinterpret_cast<__half2*>(&u);
    return __half22float2(h);
}
__device__ __forceinline__ unsigned smem_u32(const void* p) {
    return (unsigned)__cvta_generic_to_shared(p);
}
__device__ __forceinline__ void cp_async16(unsigned s, const void* g) {
    asm volatile("cp.async.cg.shared.global [%0], [%1], 16;" :: "r"(s), "l"(g));
}
__device__ __forceinline__ void cp_commit() {
    asm volatile("cp.async.commit_group;");
}
template <int N>
__device__ __forceinline__ void cp_wait() {
    asm volatile("cp.async.wait_group %0;" :: "n"(N));
}

// ------------------------------ hist ----------------------------------------
__global__ void hist_kernel(const int* __restrict__ rows, int nnz) {
    int idx = blockIdx.x * blockDim.x + threadIdx.x;
    int nv = nnz >> 2;
    if (idx < nv) {
        int4 r4 = reinterpret_cast<const int4*>(rows)[idx];
        atomicAdd(&g_cnt[r4.x], 1);
        atomicAdd(&g_cnt[r4.y], 1);
        atomicAdd(&g_cnt[r4.z], 1);
        atomicAdd(&g_cnt[r4.w], 1);
    } else if (idx == nv) {
        for (int e = nv * 4; e < nnz; e++) atomicAdd(&g_cnt[rows[e]], 1);
    }
}

// ------------------------------ scans ---------------------------------------
__global__ void scan1_kernel(int n) {
    __shared__ int s[SCAN_B];
    int tid = threadIdx.x;
    int i = blockIdx.x * SCAN_B + tid;
    int v = (i < n) ? g_cnt[i] : 0;
    s[tid] = v;
    __syncthreads();
#pragma unroll
    for (int off = 1; off < SCAN_B; off <<= 1) {
        int t = 0;
        if (tid >= off) t = s[tid - off];
        __syncthreads();
        if (tid >= off) s[tid] += t;
        __syncthreads();
    }
    if (i < n) g_ptr[i] = s[tid] - v;
    if (tid == SCAN_B - 1) g_part[blockIdx.x] = s[SCAN_B - 1];
}

__global__ void scan23_kernel(int n, int nb) {
    __shared__ int s[128];
    int tid = threadIdx.x;
    if (tid < 128) s[tid] = (tid < nb) ? g_part[tid] : 0;
    __syncthreads();
#pragma unroll
    for (int off = 1; off < 128; off <<= 1) {
        int u = 0;
        if (tid < 128 && tid >= off) u = s[tid - off];
        __syncthreads();
        if (tid < 128 && tid >= off) s[tid] += u;
        __syncthreads();
    }
    int i = blockIdx.x * blockDim.x + tid;
    if (i < n) {
        int blk = i >> 10;
        int base = (blk == 0) ? 0 : s[blk - 1];
        int p = g_ptr[i] + base;
        g_ptr[i] = p;
        g_cur[i] = p;
    }
}

// ------------------------------ fused GEMM + scatter -------------------------
// gemm blocks: 8 independent per-warp pipelines. Warp owns 32 rows; k tiled by
// 16 via private double-buffered cp.async staging. No block barriers in the
// main loop. scatter blocks: 4 edges/thread.
__global__ void __launch_bounds__(256) gemm_scatter_kernel(
        const float* __restrict__ Hm, const float* __restrict__ W1,
        const int* __restrict__ rows, const int* __restrict__ cols,
        const float* __restrict__ vals, int n, int nnz, int gemm_blocks) {
    __shared__ ull   sW2[DQ * 8];               // 32KB  [k][pair0..7]
    __shared__ float sH[8][2][32 * PADW];       // 8 x 5KB

    if ((int)blockIdx.x < gemm_blocks) {
        int tid  = threadIdx.x;
        int warp = tid >> 5;
        int lane = tid & 31;
        int rbase = (blockIdx.x * 8 + warp) * 32;
        int row   = rbase + lane;

        // W via cp.async (part of group 0)
#pragma unroll
        for (int j = 0; j < 8; j++) {
            int i = tid + 256 * j;               // 2048 float4 of W
            cp_async16(smem_u32(reinterpret_cast<float4*>(sW2) + i),
                       reinterpret_cast<const float4*>(W1) + i);
        }
        // stage tile 0 (same group 0)
#pragma unroll
        for (int j = 0; j < 4; j++) {
            int i = lane + 32 * j;               // 128 float4: row r, quad q
            int r = i >> 2, q = i & 3;
            int grow = rbase + r;
            if (grow < n)
                cp_async16(smem_u32(&sH[warp][0][r * PADW + q * 4]),
                           Hm + (size_t)grow * DQ + q * 4);
        }
        cp_commit();

        ull acc[8];
        ull z = pack2(0.f);
#pragma unroll
        for (int p = 0; p < 8; p++) acc[p] = z;

        const ulonglong2* wv = reinterpret_cast<const ulonglong2*>(sW2);

        for (int t = 0; t < NT; t++) {
            int buf = t & 1;
            if (t + 1 < NT) {
#pragma unroll
                for (int j = 0; j < 4; j++) {
                    int i = lane + 32 * j;
                    int r = i >> 2, q = i & 3;
                    int grow = rbase + r;
                    if (grow < n)
                        cp_async16(smem_u32(&sH[warp][buf ^ 1][r * PADW + q * 4]),
                                   Hm + (size_t)grow * DQ + (t + 1) * TK + q * 4);
                }
                cp_commit();
                cp_wait<1>();
            } else {
                cp_wait<0>();
            }
            __syncwarp();
            if (t == 0) __syncthreads();         // W visible to all warps

            const float* hrow = &sH[warp][buf][lane * PADW];
#pragma unroll
            for (int q = 0; q < 4; q++) {
                float4 h4 = *reinterpret_cast<const float4*>(hrow + q * 4);
                float hh[4] = {h4.x, h4.y, h4.z, h4.w};
#pragma unroll
                for (int j = 0; j < 4; j++) {
                    int k = t * TK + q * 4 + j;
                    ull hp = pack2(hh[j]);
#pragma unroll
                    for (int p = 0; p < 4; p++) {
                        ulonglong2 w = wv[k * 4 + p];
                        acc[2 * p + 0] = fma2(hp, w.x, acc[2 * p + 0]);
                        acc[2 * p + 1] = fma2(hp, w.y, acc[2 * p + 1]);
                    }
                }
            }
            __syncwarp();                        // all lanes done reading buf
        }

        if (row < n) {
            uint2* o = &g_X1h[(size_t)row * 4];
#pragma unroll
            for (int q = 0; q < 4; q++)
                o[q] = make_uint2(h2pack(acc[2 * q]), h2pack(acc[2 * q + 1]));
        }
    } else {
        int idx = (blockIdx.x - gemm_blocks) * 256 + threadIdx.x;
        int nv = nnz >> 2;
        if (idx < nv) {
            int4   r4 = reinterpret_cast<const int4*>(rows)[idx];
            int4   c4 = reinterpret_cast<const int4*>(cols)[idx];
            float4 v4 = reinterpret_cast<const float4*>(vals)[idx];
            int p0 = atomicAdd(&g_cur[r4.x], 1);
            int p1 = atomicAdd(&g_cur[r4.y], 1);
            int p2 = atomicAdd(&g_cur[r4.z], 1);
            int p3 = atomicAdd(&g_cur[r4.w], 1);
            g_edges[p0] = make_int2(c4.x, __float_as_int(v4.x));
            g_edges[p1] = make_int2(c4.y, __float_as_int(v4.y));
            g_edges[p2] = make_int2(c4.z, __float_as_int(v4.z));
            g_edges[p3] = make_int2(c4.w, __float_as_int(v4.w));
        } else if (idx == nv) {
            for (int e = nv * 4; e < nnz; e++) {
                int p = atomicAdd(&g_cur[rows[e]], 1);
                g_edges[p] = make_int2(cols[e], __float_as_int(vals[e]));
            }
        }
    }
}

// ------------------------------ SpMM 1 (MLP=4) -------------------------------
__global__ void spmm1_kernel(const float* __restrict__ b1, int n) {
    int wg   = (blockIdx.x * blockDim.x + threadIdx.x) >> 5;
    int lane = threadIdx.x & 31;
    int rloc = lane >> 2, sub = lane & 3;
    int row  = wg * 8 + rloc;
    if (row >= n) return;

    int start = g_ptr[row];
    int deg   = g_cnt[row];
    const int2* ed = g_edges + start;
    const float4 b = reinterpret_cast<const float4*>(b1)[sub];

    float4 acc = make_float4(0, 0, 0, 0);
    int i = 0;
    for (; i + 4 <= deg; i += 4) {
        int2 e0 = ed[i + 0], e1 = ed[i + 1], e2 = ed[i + 2], e3 = ed[i + 3];
        uint2 x0 = g_X1h[(size_t)e0.x * 4 + sub];
        uint2 x1 = g_X1h[(size_t)e1.x * 4 + sub];
        uint2 x2 = g_X1h[(size_t)e2.x * 4 + sub];
        uint2 x3 = g_X1h[(size_t)e3.x * 4 + sub];
        float v0 = __int_as_float(e0.y), v1 = __int_as_float(e1.y);
        float v2 = __int_as_float(e2.y), v3 = __int_as_float(e3.y);
        float2 a0 = h2unpack(x0.x), b0 = h2unpack(x0.y);
        float2 a1 = h2unpack(x1.x), b1h = h2unpack(x1.y);
        float2 a2 = h2unpack(x2.x), b2h = h2unpack(x2.y);
        float2 a3 = h2unpack(x3.x), b3h = h2unpack(x3.y);
        acc.x = fmaf(v0, a0.x, acc.x); acc.y = fmaf(v0, a0.y, acc.y);
        acc.z = fmaf(v0, b0.x, acc.z); acc.w = fmaf(v0, b0.y, acc.w);
        acc.x = fmaf(v1, a1.x, acc.x); acc.y = fmaf(v1, a1.y, acc.y);
        acc.z = fmaf(v1, b1h.x, acc.z); acc.w = fmaf(v1, b1h.y, acc.w);
        acc.x = fmaf(v2, a2.x, acc.x); acc.y = fmaf(v2, a2.y, acc.y);
        acc.z = fmaf(v2, b2h.x, acc.z); acc.w = fmaf(v2, b2h.y, acc.w);
        acc.x = fmaf(v3, a3.x, acc.x); acc.y = fmaf(v3, a3.y, acc.y);
        acc.z = fmaf(v3, b3h.x, acc.z); acc.w = fmaf(v3, b3h.y, acc.w);
    }
    for (; i < deg; i++) {
        int2 e = ed[i];
        float v = __int_as_float(e.y);
        uint2 xh = g_X1h[(size_t)e.x * 4 + sub];
        float2 x0 = h2unpack(xh.x), x1 = h2unpack(xh.y);
        acc.x = fmaf(v, x0.x, acc.x); acc.y = fmaf(v, x0.y, acc.y);
        acc.z = fmaf(v, x1.x, acc.z); acc.w = fmaf(v, x1.y, acc.w);
    }
    float2 z0 = make_float2(fmaxf(acc.x + b.x, 0.f), fmaxf(acc.y + b.y, 0.f));
    float2 z1 = make_float2(fmaxf(acc.z + b.z, 0.f), fmaxf(acc.w + b.w, 0.f));
    __half2 h0 = __float22half2_rn(z0);
    __half2 h1 = __float22half2_rn(z1);
    g_Zh[(size_t)row * 4 + sub] =
        make_uint2(*reinterpret_cast<unsigned*>(&h0), *reinterpret_cast<unsigned*>(&h1));
}

// ------------------------------ SpMM 2 + epilogue (MLP=4) --------------------
__global__ void __launch_bounds__(256) spmm2_epi_kernel(
        const float* __restrict__ W2, const float* __restrict__ b2,
        float* __restrict__ out, int n) {
    __shared__ float sY[64 * 17];
    __shared__ float sW[H1Q * CQ];
    __shared__ float sB[CQ];

    for (int i = threadIdx.x; i < H1Q * CQ; i += blockDim.x) sW[i] = W2[i];
    if (threadIdx.x < CQ) sB[threadIdx.x] = b2[threadIdx.x];

    int warp  = threadIdx.x >> 5;
    int lane  = threadIdx.x & 31;
    int rloc  = warp * 8 + (lane >> 2);
    int sub   = lane & 3;
    int rbase = blockIdx.x * 64;
    int row   = rbase + rloc;

    float4 acc = make_float4(0, 0, 0, 0);
    if (row < n) {
        int start = g_ptr[row];
        int deg   = g_cnt[row];
        const int2* ed = g_edges + start;
        int i = 0;
        for (; i + 4 <= deg; i += 4) {
            int2 e0 = ed[i + 0], e1 = ed[i + 1], e2 = ed[i + 2], e3 = ed[i + 3];
            uint2 x0 = g_Zh[(size_t)e0.x * 4 + sub];
            uint2 x1 = g_Zh[(size_t)e1.x * 4 + sub];
            uint2 x2 = g_Zh[(size_t)e2.x * 4 + sub];
            uint2 x3 = g_Zh[(size_t)e3.x * 4 + sub];
            float v0 = __int_as_float(e0.y), v1 = __int_as_float(e1.y);
            float v2 = __int_as_float(e2.y), v3 = __int_as_float(e3.y);
            float2 a0 = h2unpack(x0.x), c0 = h2unpack(x0.y);
            float2 a1 = h2unpack(x1.x), c1 = h2unpack(x1.y);
            float2 a2 = h2unpack(x2.x), c2 = h2unpack(x2.y);
            float2 a3 = h2unpack(x3.x), c3 = h2unpack(x3.y);
            acc.x = fmaf(v0, a0.x, acc.x); acc.y = fmaf(v0, a0.y, acc.y);
            acc.z = fmaf(v0, c0.x, acc.z); acc.w = fmaf(v0, c0.y, acc.w);
            acc.x = fmaf(v1, a1.x, acc.x); acc.y = fmaf(v1, a1.y, acc.y);
            acc.z = fmaf(v1, c1.x, acc.z); acc.w = fmaf(v1, c1.y, acc.w);
            acc.x = fmaf(v2, a2.x, acc.x); acc.y = fmaf(v2, a2.y, acc.y);
            acc.z = fmaf(v2, c2.x, acc.z); acc.w = fmaf(v2, c2.y, acc.w);
            acc.x = fmaf(v3, a3.x, acc.x); acc.y = fmaf(v3, a3.y, acc.y);
            acc.z = fmaf(v3, c3.x, acc.z); acc.w = fmaf(v3, c3.y, acc.w);
        }
        for (; i < deg; i++) {
            int2 e = ed[i];
            float v = __int_as_float(e.y);
            uint2 xh = g_Zh[(size_t)e.x * 4 + sub];
            float2 x0 = h2unpack(xh.x), x1 = h2unpack(xh.y);
            acc.x = fmaf(v, x0.x, acc.x); acc.y = fmaf(v, x0.y, acc.y);
            acc.z = fmaf(v, x1.x, acc.z); acc.w = fmaf(v, x1.y, acc.w);
        }
    }
    float* sy = &sY[rloc * 17 + sub * 4];
    sy[0] = acc.x; sy[1] = acc.y; sy[2] = acc.z; sy[3] = acc.w;
    __syncthreads();

    int t = threadIdx.x;
    if (t < 64 && rbase + t < n) {
        float y[16];
#pragma unroll
        for (int k = 0; k < 16; k++) y[k] = sY[t * 17 + k];

        float o[CQ];
#pragma unroll
        for (int c = 0; c < CQ; c++) o[c] = sB[c];
#pragma unroll
        for (int k = 0; k < H1Q; k++) {
            float h = y[k];
#pragma unroll
            for (int c = 0; c < CQ; c++) o[c] = fmaf(h, sW[k * CQ + c], o[c]);
        }
        float m = 0.f;
#pragma unroll
        for (int c = 0; c < CQ; c++) {
            o[c] = fmaxf(o[c], 0.f);
            m = fmaxf(m, o[c]);
        }
        float s = 0.f;
#pragma unroll
        for (int c = 0; c < CQ; c++) s += __expf(o[c] - m);
        float l = __logf(s) + m;

        float4* op = reinterpret_cast<float4*>(out + (size_t)(rbase + t) * CQ);
#pragma unroll
        for (int q = 0; q < CQ / 4; q++)
            op[q] = make_float4(o[4 * q] - l, o[4 * q + 1] - l,
                                o[4 * q + 2] - l, o[4 * q + 3] - l);
    }
}

// ---------------------------------------------------------------------------
// Inputs (metadata order): H, A_vals, W1, b1, W2, b2, A_rows, A_cols
// ---------------------------------------------------------------------------
extern "C" void kernel_launch(void* const* d_in, const int* in_sizes, int n_in,
                              void* d_out, int out_size) {
    const float* Hm     = (const float*)d_in[0];
    const float* A_vals = (const float*)d_in[1];
    const float* W1     = (const float*)d_in[2];
    const float* b1     = (const float*)d_in[3];
    const float* W2     = (const float*)d_in[4];
    const float* b2     = (const float*)d_in[5];
    const int*   A_rows = (const int*)d_in[6];
    const int*   A_cols = (const int*)d_in[7];

    int n   = in_sizes[0] / DQ;
    int nnz = in_sizes[1];
    float* out = (float*)d_out;

    int nb_scan = (n + SCAN_B - 1) / SCAN_B;

    void* cnt_ptr = nullptr;
    cudaGetSymbolAddress(&cnt_ptr, g_cnt);
    cudaMemsetAsync(cnt_ptr, 0, (size_t)n * sizeof(int), 0);

    hist_kernel<<<(nnz / 4 + 256) / 256, 256>>>(A_rows, nnz);
    scan1_kernel<<<nb_scan, SCAN_B>>>(n);
    scan23_kernel<<<(n + 255) / 256, 256>>>(n, nb_scan);

    int gemm_blocks    = (n + 255) / 256;
    int scatter_blocks = (nnz / 4 + 256) / 256;
    gemm_scatter_kernel<<<gemm_blocks + scatter_blocks, 256>>>(
        Hm, W1, A_rows, A_cols, A_vals, n, nnz, gemm_blocks);

    spmm1_kernel<<<(n + 63) / 64, 256>>>(b1, n);
    spmm2_epi_kernel<<<(n + 63) / 64, 256>>>(W2, b2, out, n);
}

// round 9
// speedup vs baseline: 1.3979x; 1.1428x over previous
#include <cuda_runtime.h>
#include <cuda_fp16.h>

typedef unsigned long long ull;

#define DQ    512
#define H1Q   16
#define CQ    40
#define N_MAX 100000
#define NNZ_MAX 3200000
#define SCAN_B 1024
#define NBLK_SCAN ((N_MAX + SCAN_B - 1) / SCAN_B)   // 98

#define TK     8                  // k-cols per tile
#define NT     (DQ / TK)          // 64 tiles
#define PADW   12                 // floats per staged row (8 + 4 pad)

// ------------------------------ scratch -------------------------------------
__device__ uint2 g_X1h[N_MAX * 4];           // H @ W1, fp16
__device__ uint2 g_Zh [N_MAX * 4];           // relu(A @ X1 + b1), fp16
__device__ int   g_cnt[N_MAX];
__device__ int   g_ptr[N_MAX];
__device__ int   g_cur[N_MAX];
__device__ int   g_part[NBLK_SCAN];
__device__ int2  g_edges[NNZ_MAX];           // {col, val_bits} CSR-ordered

// ------------------------------ helpers -------------------------------------
__device__ __forceinline__ ull fma2(ull a, ull b, ull c) {
    ull d;
    asm("fma.rn.f32x2 %0, %1, %2, %3;" : "=l"(d) : "l"(a), "l"(b), "l"(c));
    return d;
}
__device__ __forceinline__ ull pack2(float x) {
    ull d;
    asm("mov.b64 %0, {%1, %1};" : "=l"(d) : "f"(x));
    return d;
}
__device__ __forceinline__ float2 unpack2(ull v) {
    float a, b;
    asm("mov.b64 {%0, %1}, %2;" : "=f"(a), "=f"(b) : "l"(v));
    return make_float2(a, b);
}
__device__ __forceinline__ unsigned h2pack(ull v) {
    float2 f = unpack2(v);
    __half2 h = __float22half2_rn(f);
    return *reinterpret_cast<unsigned*>(&h);
}
__device__ __forceinline__ float2 h2unpack(unsigned u) {
    __half2 h = *reinterpret_cast<__half2*>(&u);
    return __half22float2(h);
}
__device__ __forceinline__ unsigned smem_u32(const void* p) {
    return (unsigned)__cvta_generic_to_shared(p);
}
__device__ __forceinline__ void cp_async16(unsigned s, const void* g) {
    asm volatile("cp.async.cg.shared.global [%0], [%1], 16;" :: "r"(s), "l"(g));
}
__device__ __forceinline__ void cp_commit() {
    asm volatile("cp.async.commit_group;");
}
template <int N>
__device__ __forceinline__ void cp_wait() {
    asm volatile("cp.async.wait_group %0;" :: "n"(N));
}

// ------------------------------ hist ----------------------------------------
__global__ void hist_kernel(const int* __restrict__ rows, int nnz) {
    int idx = blockIdx.x * blockDim.x + threadIdx.x;
    int nv = nnz >> 2;
    if (idx < nv) {
        int4 r4 = reinterpret_cast<const int4*>(rows)[idx];
        atomicAdd(&g_cnt[r4.x], 1);
        atomicAdd(&g_cnt[r4.y], 1);
        atomicAdd(&g_cnt[r4.z], 1);
        atomicAdd(&g_cnt[r4.w], 1);
    } else if (idx == nv) {
        for (int e = nv * 4; e < nnz; e++) atomicAdd(&g_cnt[rows[e]], 1);
    }
}

// ------------------------------ scans ---------------------------------------
__global__ void scan1_kernel(int n) {
    __shared__ int s[SCAN_B];
    int tid = threadIdx.x;
    int i = blockIdx.x * SCAN_B + tid;
    int v = (i < n) ? g_cnt[i] : 0;
    s[tid] = v;
    __syncthreads();
#pragma unroll
    for (int off = 1; off < SCAN_B; off <<= 1) {
        int t = 0;
        if (tid >= off) t = s[tid - off];
        __syncthreads();
        if (tid >= off) s[tid] += t;
        __syncthreads();
    }
    if (i < n) g_ptr[i] = s[tid] - v;
    if (tid == SCAN_B - 1) g_part[blockIdx.x] = s[SCAN_B - 1];
}

__global__ void scan23_kernel(int n, int nb) {
    __shared__ int s[128];
    int tid = threadIdx.x;
    if (tid < 128) s[tid] = (tid < nb) ? g_part[tid] : 0;
    __syncthreads();
#pragma unroll
    for (int off = 1; off < 128; off <<= 1) {
        int u = 0;
        if (tid < 128 && tid >= off) u = s[tid - off];
        __syncthreads();
        if (tid < 128 && tid >= off) s[tid] += u;
        __syncthreads();
    }
    int i = blockIdx.x * blockDim.x + tid;
    if (i < n) {
        int blk = i >> 10;
        int base = (blk == 0) ? 0 : s[blk - 1];
        int p = g_ptr[i] + base;
        g_ptr[i] = p;
        g_cur[i] = p;
    }
}

// ------------------------------ fused GEMM + scatter -------------------------
// gemm blocks: 8 per-warp pipelines; warp owns 64 rows (2 rows/thread) so each
// W broadcast amortizes over 2x rows. TK=8 double-buffered cp.async staging.
// scatter blocks: 4 edges/thread.
__global__ void __launch_bounds__(256) gemm_scatter_kernel(
        const float* __restrict__ Hm, const float* __restrict__ W1,
        const int* __restrict__ rows, const int* __restrict__ cols,
        const float* __restrict__ vals, int n, int nnz, int gemm_blocks) {
    __shared__ ull   sW2[DQ * 8];               // 32KB  [k][pair0..7]
    __shared__ float sH[8][2][64 * PADW];       // 8 x 6KB

    if ((int)blockIdx.x < gemm_blocks) {
        int tid  = threadIdx.x;
        int warp = tid >> 5;
        int lane = tid & 31;
        int rbase = (blockIdx.x * 8 + warp) * 64;
        int ra = rbase + lane;
        int rb = ra + 32;

        // W via cp.async (group 0)
#pragma unroll
        for (int j = 0; j < 8; j++) {
            int i = tid + 256 * j;               // 2048 float4 of W
            cp_async16(smem_u32(reinterpret_cast<float4*>(sW2) + i),
                       reinterpret_cast<const float4*>(W1) + i);
        }
        // stage tile 0 (group 0): 64 rows x 32B = 128 x 16B chunks
#pragma unroll
        for (int j = 0; j < 4; j++) {
            int i = lane + 32 * j;
            int r = i >> 1, q = i & 1;
            int grow = rbase + r;
            if (grow < n)
                cp_async16(smem_u32(&sH[warp][0][r * PADW + q * 4]),
                           Hm + (size_t)grow * DQ + q * 4);
        }
        cp_commit();

        ull accA[8], accB[8];
        ull z = pack2(0.f);
#pragma unroll
        for (int p = 0; p < 8; p++) { accA[p] = z; accB[p] = z; }

        const ulonglong2* wv = reinterpret_cast<const ulonglong2*>(sW2);

        for (int t = 0; t < NT; t++) {
            int buf = t & 1;
            if (t + 1 < NT) {
#pragma unroll
                for (int j = 0; j < 4; j++) {
                    int i = lane + 32 * j;
                    int r = i >> 1, q = i & 1;
                    int grow = rbase + r;
                    if (grow < n)
                        cp_async16(smem_u32(&sH[warp][buf ^ 1][r * PADW + q * 4]),
                                   Hm + (size_t)grow * DQ + (t + 1) * TK + q * 4);
                }
                cp_commit();
                cp_wait<1>();
            } else {
                cp_wait<0>();
            }
            __syncwarp();
            if (t == 0) __syncthreads();         // W visible to all warps

            const float* hrA = &sH[warp][buf][lane * PADW];
            const float* hrB = &sH[warp][buf][(lane + 32) * PADW];
#pragma unroll
            for (int q = 0; q < 2; q++) {
                float4 hA = *reinterpret_cast<const float4*>(hrA + q * 4);
                float4 hB = *reinterpret_cast<const float4*>(hrB + q * 4);
                float a4[4] = {hA.x, hA.y, hA.z, hA.w};
                float b4[4] = {hB.x, hB.y, hB.z, hB.w};
#pragma unroll
                for (int j = 0; j < 4; j++) {
                    int k = t * TK + q * 4 + j;
                    ull pa = pack2(a4[j]);
                    ull pb = pack2(b4[j]);
#pragma unroll
                    for (int p = 0; p < 4; p++) {
                        ulonglong2 w = wv[k * 4 + p];
                        accA[2 * p + 0] = fma2(pa, w.x, accA[2 * p + 0]);
                        accA[2 * p + 1] = fma2(pa, w.y, accA[2 * p + 1]);
                        accB[2 * p + 0] = fma2(pb, w.x, accB[2 * p + 0]);
                        accB[2 * p + 1] = fma2(pb, w.y, accB[2 * p + 1]);
                    }
                }
            }
            __syncwarp();
        }

        if (ra < n) {
            uint2* o = &g_X1h[(size_t)ra * 4];
#pragma unroll
            for (int q = 0; q < 4; q++)
                o[q] = make_uint2(h2pack(accA[2 * q]), h2pack(accA[2 * q + 1]));
        }
        if (rb < n) {
            uint2* o = &g_X1h[(size_t)rb * 4];
#pragma unroll
            for (int q = 0; q < 4; q++)
                o[q] = make_uint2(h2pack(accB[2 * q]), h2pack(accB[2 * q + 1]));
        }
    } else {
        int idx = (blockIdx.x - gemm_blocks) * 256 + threadIdx.x;
        int nv = nnz >> 2;
        if (idx < nv) {
            int4   r4 = reinterpret_cast<const int4*>(rows)[idx];
            int4   c4 = reinterpret_cast<const int4*>(cols)[idx];
            float4 v4 = reinterpret_cast<const float4*>(vals)[idx];
            int p0 = atomicAdd(&g_cur[r4.x], 1);
            int p1 = atomicAdd(&g_cur[r4.y], 1);
            int p2 = atomicAdd(&g_cur[r4.z], 1);
            int p3 = atomicAdd(&g_cur[r4.w], 1);
            g_edges[p0] = make_int2(c4.x, __float_as_int(v4.x));
            g_edges[p1] = make_int2(c4.y, __float_as_int(v4.y));
            g_edges[p2] = make_int2(c4.z, __float_as_int(v4.z));
            g_edges[p3] = make_int2(c4.w, __float_as_int(v4.w));
        } else if (idx == nv) {
            for (int e = nv * 4; e < nnz; e++) {
                int p = atomicAdd(&g_cur[rows[e]], 1);
                g_edges[p] = make_int2(cols[e], __float_as_int(vals[e]));
            }
        }
    }
}

// ------------------------------ SpMM 1 (MLP=4) -------------------------------
__global__ void spmm1_kernel(const float* __restrict__ b1, int n) {
    int wg   = (blockIdx.x * blockDim.x + threadIdx.x) >> 5;
    int lane = threadIdx.x & 31;
    int rloc = lane >> 2, sub = lane & 3;
    int row  = wg * 8 + rloc;
    if (row >= n) return;

    int start = g_ptr[row];
    int deg   = g_cnt[row];
    const int2* ed = g_edges + start;
    const float4 b = reinterpret_cast<const float4*>(b1)[sub];

    float4 acc = make_float4(0, 0, 0, 0);
    int i = 0;
    for (; i + 4 <= deg; i += 4) {
        int2 e0 = ed[i + 0], e1 = ed[i + 1], e2 = ed[i + 2], e3 = ed[i + 3];
        uint2 x0 = g_X1h[(size_t)e0.x * 4 + sub];
        uint2 x1 = g_X1h[(size_t)e1.x * 4 + sub];
        uint2 x2 = g_X1h[(size_t)e2.x * 4 + sub];
        uint2 x3 = g_X1h[(size_t)e3.x * 4 + sub];
        float v0 = __int_as_float(e0.y), v1 = __int_as_float(e1.y);
        float v2 = __int_as_float(e2.y), v3 = __int_as_float(e3.y);
        float2 a0 = h2unpack(x0.x), b0 = h2unpack(x0.y);
        float2 a1 = h2unpack(x1.x), b1h = h2unpack(x1.y);
        float2 a2 = h2unpack(x2.x), b2h = h2unpack(x2.y);
        float2 a3 = h2unpack(x3.x), b3h = h2unpack(x3.y);
        acc.x = fmaf(v0, a0.x, acc.x); acc.y = fmaf(v0, a0.y, acc.y);
        acc.z = fmaf(v0, b0.x, acc.z); acc.w = fmaf(v0, b0.y, acc.w);
        acc.x = fmaf(v1, a1.x, acc.x); acc.y = fmaf(v1, a1.y, acc.y);
        acc.z = fmaf(v1, b1h.x, acc.z); acc.w = fmaf(v1, b1h.y, acc.w);
        acc.x = fmaf(v2, a2.x, acc.x); acc.y = fmaf(v2, a2.y, acc.y);
        acc.z = fmaf(v2, b2h.x, acc.z); acc.w = fmaf(v2, b2h.y, acc.w);
        acc.x = fmaf(v3, a3.x, acc.x); acc.y = fmaf(v3, a3.y, acc.y);
        acc.z = fmaf(v3, b3h.x, acc.z); acc.w = fmaf(v3, b3h.y, acc.w);
    }
    for (; i < deg; i++) {
        int2 e = ed[i];
        float v = __int_as_float(e.y);
        uint2 xh = g_X1h[(size_t)e.x * 4 + sub];
        float2 x0 = h2unpack(xh.x), x1 = h2unpack(xh.y);
        acc.x = fmaf(v, x0.x, acc.x); acc.y = fmaf(v, x0.y, acc.y);
        acc.z = fmaf(v, x1.x, acc.z); acc.w = fmaf(v, x1.y, acc.w);
    }
    float2 z0 = make_float2(fmaxf(acc.x + b.x, 0.f), fmaxf(acc.y + b.y, 0.f));
    float2 z1 = make_float2(fmaxf(acc.z + b.z, 0.f), fmaxf(acc.w + b.w, 0.f));
    __half2 h0 = __float22half2_rn(z0);
    __half2 h1 = __float22half2_rn(z1);
    g_Zh[(size_t)row * 4 + sub] =
        make_uint2(*reinterpret_cast<unsigned*>(&h0), *reinterpret_cast<unsigned*>(&h1));
}

// ------------------------------ SpMM 2 + epilogue (MLP=4) --------------------
__global__ void __launch_bounds__(256) spmm2_epi_kernel(
        const float* __restrict__ W2, const float* __restrict__ b2,
        float* __restrict__ out, int n) {
    __shared__ float sY[64 * 17];
    __shared__ float sW[H1Q * CQ];
    __shared__ float sB[CQ];

    for (int i = threadIdx.x; i < H1Q * CQ; i += blockDim.x) sW[i] = W2[i];
    if (threadIdx.x < CQ) sB[threadIdx.x] = b2[threadIdx.x];

    int warp  = threadIdx.x >> 5;
    int lane  = threadIdx.x & 31;
    int rloc  = warp * 8 + (lane >> 2);
    int sub   = lane & 3;
    int rbase = blockIdx.x * 64;
    int row   = rbase + rloc;

    float4 acc = make_float4(0, 0, 0, 0);
    if (row < n) {
        int start = g_ptr[row];
        int deg   = g_cnt[row];
        const int2* ed = g_edges + start;
        int i = 0;
        for (; i + 4 <= deg; i += 4) {
            int2 e0 = ed[i + 0], e1 = ed[i + 1], e2 = ed[i + 2], e3 = ed[i + 3];
            uint2 x0 = g_Zh[(size_t)e0.x * 4 + sub];
            uint2 x1 = g_Zh[(size_t)e1.x * 4 + sub];
            uint2 x2 = g_Zh[(size_t)e2.x * 4 + sub];
            uint2 x3 = g_Zh[(size_t)e3.x * 4 + sub];
            float v0 = __int_as_float(e0.y), v1 = __int_as_float(e1.y);
            float v2 = __int_as_float(e2.y), v3 = __int_as_float(e3.y);
            float2 a0 = h2unpack(x0.x), c0 = h2unpack(x0.y);
            float2 a1 = h2unpack(x1.x), c1 = h2unpack(x1.y);
            float2 a2 = h2unpack(x2.x), c2 = h2unpack(x2.y);
            float2 a3 = h2unpack(x3.x), c3 = h2unpack(x3.y);
            acc.x = fmaf(v0, a0.x, acc.x); acc.y = fmaf(v0, a0.y, acc.y);
            acc.z = fmaf(v0, c0.x, acc.z); acc.w = fmaf(v0, c0.y, acc.w);
            acc.x = fmaf(v1, a1.x, acc.x); acc.y = fmaf(v1, a1.y, acc.y);
            acc.z = fmaf(v1, c1.x, acc.z); acc.w = fmaf(v1, c1.y, acc.w);
            acc.x = fmaf(v2, a2.x, acc.x); acc.y = fmaf(v2, a2.y, acc.y);
            acc.z = fmaf(v2, c2.x, acc.z); acc.w = fmaf(v2, c2.y, acc.w);
            acc.x = fmaf(v3, a3.x, acc.x); acc.y = fmaf(v3, a3.y, acc.y);
            acc.z = fmaf(v3, c3.x, acc.z); acc.w = fmaf(v3, c3.y, acc.w);
        }
        for (; i < deg; i++) {
            int2 e = ed[i];
            float v = __int_as_float(e.y);
            uint2 xh = g_Zh[(size_t)e.x * 4 + sub];
            float2 x0 = h2unpack(xh.x), x1 = h2unpack(xh.y);
            acc.x = fmaf(v, x0.x, acc.x); acc.y = fmaf(v, x0.y, acc.y);
            acc.z = fmaf(v, x1.x, acc.z); acc.w = fmaf(v, x1.y, acc.w);
        }
    }
    float* sy = &sY[rloc * 17 + sub * 4];
    sy[0] = acc.x; sy[1] = acc.y; sy[2] = acc.z; sy[3] = acc.w;
    __syncthreads();

    int t = threadIdx.x;
    if (t < 64 && rbase + t < n) {
        float y[16];
#pragma unroll
        for (int k = 0; k < 16; k++) y[k] = sY[t * 17 + k];

        float o[CQ];
#pragma unroll
        for (int c = 0; c < CQ; c++) o[c] = sB[c];
#pragma unroll
        for (int k = 0; k < H1Q; k++) {
            float h = y[k];
#pragma unroll
            for (int c = 0; c < CQ; c++) o[c] = fmaf(h, sW[k * CQ + c], o[c]);
        }
        float m = 0.f;
#pragma unroll
        for (int c = 0; c < CQ; c++) {
            o[c] = fmaxf(o[c], 0.f);
            m = fmaxf(m, o[c]);
        }
        float s = 0.f;
#pragma unroll
        for (int c = 0; c < CQ; c++) s += __expf(o[c] - m);
        float l = __logf(s) + m;

        float4* op = reinterpret_cast<float4*>(out + (size_t)(rbase + t) * CQ);
#pragma unroll
        for (int q = 0; q < CQ / 4; q++)
            op[q] = make_float4(o[4 * q] - l, o[4 * q + 1] - l,
                                o[4 * q + 2] - l, o[4 * q + 3] - l);
    }
}

// ---------------------------------------------------------------------------
// Inputs (metadata order): H, A_vals, W1, b1, W2, b2, A_rows, A_cols
// ---------------------------------------------------------------------------
extern "C" void kernel_launch(void* const* d_in, const int* in_sizes, int n_in,
                              void* d_out, int out_size) {
    const float* Hm     = (const float*)d_in[0];
    const float* A_vals = (const float*)d_in[1];
    const float* W1     = (const float*)d_in[2];
    const float* b1     = (const float*)d_in[3];
    const float* W2     = (const float*)d_in[4];
    const float* b2     = (const float*)d_in[5];
    const int*   A_rows = (const int*)d_in[6];
    const int*   A_cols = (const int*)d_in[7];

    int n   = in_sizes[0] / DQ;
    int nnz = in_sizes[1];
    float* out = (float*)d_out;

    int nb_scan = (n + SCAN_B - 1) / SCAN_B;

    void* cnt_ptr = nullptr;
    cudaGetSymbolAddress(&cnt_ptr, g_cnt);
    cudaMemsetAsync(cnt_ptr, 0, (size_t)n * sizeof(int), 0);

    hist_kernel<<<(nnz / 4 + 256) / 256, 256>>>(A_rows, nnz);
    scan1_kernel<<<nb_scan, SCAN_B>>>(n);
    scan23_kernel<<<(n + 255) / 256, 256>>>(n, nb_scan);

    int gemm_blocks    = (n + 511) / 512;
    int scatter_blocks = (nnz / 4 + 256) / 256;
    gemm_scatter_kernel<<<gemm_blocks + scatter_blocks, 256>>>(
        Hm, W1, A_rows, A_cols, A_vals, n, nnz, gemm_blocks);

    spmm1_kernel<<<(n + 63) / 64, 256>>>(b1, n);
    spmm2_epi_kernel<<<(n + 63) / 64, 256>>>(W2, b2, out, n);
}